// round 15
// baseline (speedup 1.0000x reference)
#include <cuda_runtime.h>
#include <cuda_bf16.h>
#include <cstdint>

constexpr int Bsz = 16;
constexpr int Sq  = 1024;
constexpr int Hd  = 1024;
constexpr int Dd  = 128;

__device__ uint16_t g_qh[Bsz * Sq * Dd], g_ql[Bsz * Sq * Dd];
__device__ uint16_t g_kh[Bsz * Sq * Dd], g_kl[Bsz * Sq * Dd];
__device__ uint16_t g_vTh[Dd * Bsz * Sq], g_vTl[Dd * Bsz * Sq];   // vT[d][b*S+t]
__device__ uint16_t g_wh[(size_t)Bsz * Sq * Sq], g_wl[(size_t)Bsz * Sq * Sq];
__device__ float    g_scores[(size_t)Bsz * Sq * Sq];

// ======================= helpers =======================
__device__ __forceinline__ uint32_t smem_u32(const void* p) {
    uint32_t a;
    asm("{ .reg .u64 t; cvta.to.shared.u64 t, %1; cvt.u32.u64 %0, t; }" : "=r"(a) : "l"(p));
    return a;
}
__device__ __forceinline__ void ldsm4(uint32_t addr, uint32_t* r) {
    asm volatile("ldmatrix.sync.aligned.m8n8.x4.shared.b16 {%0,%1,%2,%3}, [%4];"
                 : "=r"(r[0]), "=r"(r[1]), "=r"(r[2]), "=r"(r[3]) : "r"(addr));
}
__device__ __forceinline__ void ldsm4t(uint32_t addr, uint32_t* r) {
    asm volatile("ldmatrix.sync.aligned.m8n8.x4.trans.shared.b16 {%0,%1,%2,%3}, [%4];"
                 : "=r"(r[0]), "=r"(r[1]), "=r"(r[2]), "=r"(r[3]) : "r"(addr));
}
__device__ __forceinline__ void mma16816(float* c, const uint32_t* a, uint32_t b0, uint32_t b1) {
    asm volatile(
        "mma.sync.aligned.m16n8k16.row.col.f32.bf16.bf16.f32 "
        "{%0,%1,%2,%3}, {%4,%5,%6,%7}, {%8,%9}, {%0,%1,%2,%3};"
        : "+f"(c[0]), "+f"(c[1]), "+f"(c[2]), "+f"(c[3])
        : "r"(a[0]), "r"(a[1]), "r"(a[2]), "r"(a[3]), "r"(b0), "r"(b1));
}
__device__ __forceinline__ float4 ldcs4(const float* p) {
    float4 v;
    asm volatile("ld.global.cs.v4.f32 {%0,%1,%2,%3}, [%4];"
                 : "=f"(v.x), "=f"(v.y), "=f"(v.z), "=f"(v.w) : "l"(p));
    return v;
}
__device__ __forceinline__ void stcs2(void* p, uint2 v) {
    asm volatile("st.global.cs.v2.u32 [%0], {%1,%2};" :: "l"(p), "r"(v.x), "r"(v.y) : "memory");
}
__device__ __forceinline__ void bf16x3_split(float4 v, uint32_t& h01, uint32_t& h23,
                                             uint32_t& l01, uint32_t& l23) {
    asm("cvt.rn.bf16x2.f32 %0, %1, %2;" : "=r"(h01) : "f"(v.y), "f"(v.x));
    asm("cvt.rn.bf16x2.f32 %0, %1, %2;" : "=r"(h23) : "f"(v.w), "f"(v.z));
    float h0 = __uint_as_float(h01 << 16);
    float h1 = __uint_as_float(h01 & 0xffff0000u);
    float h2 = __uint_as_float(h23 << 16);
    float h3 = __uint_as_float(h23 & 0xffff0000u);
    float l0 = v.x - h0, l1 = v.y - h1, l2 = v.z - h2, l3 = v.w - h3;
    asm("cvt.rn.bf16x2.f32 %0, %1, %2;" : "=r"(l01) : "f"(l1), "f"(l0));
    asm("cvt.rn.bf16x2.f32 %0, %1, %2;" : "=r"(l23) : "f"(l3), "f"(l2));
}
__device__ __forceinline__ void split2(float2 v, uint32_t& h, uint32_t& l) {
    asm("cvt.rn.bf16x2.f32 %0, %1, %2;" : "=r"(h) : "f"(v.y), "f"(v.x));
    float h0 = __uint_as_float(h << 16);
    float h1 = __uint_as_float(h & 0xffff0000u);
    float l0 = v.x - h0, l1 = v.y - h1;
    asm("cvt.rn.bf16x2.f32 %0, %1, %2;" : "=r"(l) : "f"(l1), "f"(l0));
}

constexpr int KPAD = 72;
constexpr int PLB  = 128 * KPAD * 2;
constexpr int SMEM_GEMM = 8 * PLB;   // 147456

// ======================= fused projection kernel (R9 + ldcs on A) =======================
__global__ void __launch_bounds__(256, 1)
proj_kernel(const float* __restrict__ query, const float* __restrict__ key_,
            const float* __restrict__ value,
            const float* __restrict__ Wq, const float* __restrict__ bq,
            const float* __restrict__ Wk, const float* __restrict__ bk,
            const float* __restrict__ Wv, const float* __restrict__ bv)
{
    extern __shared__ char sm[];
    const uint32_t sb = smem_u32(sm);
    const int tid = threadIdx.x, lane = tid & 31, wid = tid >> 5;
    const int wm = wid >> 2, wn = wid & 3;
    const int z = blockIdx.z;
    const int bm0 = blockIdx.y * 128;

    const float *A, *Bw, *bias;
    if (z == 0)      { A = query; Bw = Wq; bias = bq; }
    else if (z == 1) { A = key_;  Bw = Wk; bias = bk; }
    else             { A = value; Bw = Wv; bias = bv; }
    const float* Ab = A + (long long)bm0 * Hd;

    float acc[4][4][4];
#pragma unroll
    for (int i = 0; i < 4; ++i)
#pragma unroll
        for (int j = 0; j < 4; ++j)
#pragma unroll
            for (int r = 0; r < 4; ++r) acc[i][j][r] = 0.f;

    const int r0 = tid >> 4;
    const int c4 = tid & 15;
    const int nch = Hd >> 6;

    float4 ra[8], rb[8];
#pragma unroll
    for (int i = 0; i < 8; ++i) {
        const int r = r0 + i * 16;
        ra[i] = ldcs4(Ab + (long long)r * Hd + (c4 << 2));
        rb[i] = *(const float4*)(Bw + (long long)r * Hd + (c4 << 2));
    }
    {
        char* base = sm;
#pragma unroll
        for (int i = 0; i < 8; ++i) {
            const int r = r0 + i * 16;
            const uint32_t off = (uint32_t)(r * KPAD + (c4 << 2)) * 2;
            uint32_t h01, h23, l01, l23;
            bf16x3_split(ra[i], h01, h23, l01, l23);
            *(uint2*)(base + off)       = make_uint2(h01, h23);
            *(uint2*)(base + PLB + off) = make_uint2(l01, l23);
            bf16x3_split(rb[i], h01, h23, l01, l23);
            *(uint2*)(base + 2 * PLB + off) = make_uint2(h01, h23);
            *(uint2*)(base + 3 * PLB + off) = make_uint2(l01, l23);
        }
    }
    __syncthreads();

    const int lrow = lane & 15;
    const int lk   = (lane >> 4) << 3;

    for (int c = 0; c < nch; ++c) {
        const bool more = (c + 1) < nch;
        if (more) {
            const float* Ac = Ab + (c + 1) * 64;
            const float* Bc = Bw + (c + 1) * 64;
#pragma unroll
            for (int i = 0; i < 8; ++i) {
                const int r = r0 + i * 16;
                ra[i] = ldcs4(Ac + (long long)r * Hd + (c4 << 2));
                rb[i] = *(const float4*)(Bc + (long long)r * Hd + (c4 << 2));
            }
        }
        const uint32_t bo = (uint32_t)(c & 1) * 4u * PLB;
#pragma unroll
        for (int ks = 0; ks < 4; ++ks) {
            const int k0 = ks * 16;
            uint32_t Ah[4][4], Al[4][4], Bh[2][4], Bl[2][4];
#pragma unroll
            for (int i = 0; i < 4; ++i) {
                const uint32_t ro = (uint32_t)((wm * 64 + i * 16 + lrow) * KPAD + k0 + lk) * 2;
                ldsm4(sb + bo + ro, Ah[i]);
                ldsm4(sb + bo + PLB + ro, Al[i]);
            }
#pragma unroll
            for (int jj = 0; jj < 2; ++jj) {
                const uint32_t ro = (uint32_t)((wn * 32 + jj * 16 + lrow) * KPAD + k0 + lk) * 2;
                ldsm4(sb + bo + 2 * PLB + ro, Bh[jj]);
                ldsm4(sb + bo + 3 * PLB + ro, Bl[jj]);
            }
#pragma unroll
            for (int i = 0; i < 4; ++i)
#pragma unroll
                for (int j = 0; j < 4; ++j) {
                    const int jj = j >> 1, ss = j & 1;
                    mma16816(acc[i][j], Ah[i], Bh[jj][ss], Bh[jj][ss + 2]);
                    mma16816(acc[i][j], Ah[i], Bl[jj][ss], Bl[jj][ss + 2]);
                    mma16816(acc[i][j], Al[i], Bh[jj][ss], Bh[jj][ss + 2]);
                }
        }
        if (more) {
            char* base = sm + ((c + 1) & 1) * 4 * PLB;
#pragma unroll
            for (int i = 0; i < 8; ++i) {
                const int r = r0 + i * 16;
                const uint32_t off = (uint32_t)(r * KPAD + (c4 << 2)) * 2;
                uint32_t h01, h23, l01, l23;
                bf16x3_split(ra[i], h01, h23, l01, l23);
                *(uint2*)(base + off)       = make_uint2(h01, h23);
                *(uint2*)(base + PLB + off) = make_uint2(l01, l23);
                bf16x3_split(rb[i], h01, h23, l01, l23);
                *(uint2*)(base + 2 * PLB + off) = make_uint2(h01, h23);
                *(uint2*)(base + 3 * PLB + off) = make_uint2(l01, l23);
            }
        }
        __syncthreads();
    }

    uint16_t *Oh, *Ol;
    if (z == 0)      { Oh = g_qh;  Ol = g_ql; }
    else if (z == 1) { Oh = g_kh;  Ol = g_kl; }
    else             { Oh = g_vTh; Ol = g_vTl; }
    const int g  = lane >> 2;
    const int tq = lane & 3;
#pragma unroll
    for (int i = 0; i < 4; ++i)
#pragma unroll
        for (int j = 0; j < 4; ++j) {
            const int row = bm0 + wm * 64 + i * 16 + g;
            const int col = wn * 32 + j * 8 + tq * 2;
#pragma unroll
            for (int h = 0; h < 2; ++h) {
                const int rr = row + h * 8;
                float v0 = acc[i][j][h * 2 + 0] + bias[col];
                float v1 = acc[i][j][h * 2 + 1] + bias[col + 1];
                uint32_t hh, ll;
                split2(make_float2(v0, v1), hh, ll);
                if (z < 2) {
                    *(uint32_t*)&Oh[(size_t)rr * Dd + col] = hh;
                    *(uint32_t*)&Ol[(size_t)rr * Dd + col] = ll;
                } else {
                    Oh[(size_t)col * (Bsz * Sq) + rr]       = (uint16_t)(hh & 0xffff);
                    Oh[(size_t)(col + 1) * (Bsz * Sq) + rr] = (uint16_t)(hh >> 16);
                    Ol[(size_t)col * (Bsz * Sq) + rr]       = (uint16_t)(ll & 0xffff);
                    Ol[(size_t)(col + 1) * (Bsz * Sq) + rr] = (uint16_t)(ll >> 16);
                }
            }
        }
}

// ======================= attn1 GEMM (R9, unchanged) =======================
__global__ void __launch_bounds__(256, 1)
bf16_gemm_kernel(const uint16_t* __restrict__ Ah_, const uint16_t* __restrict__ Al_,
                 const uint16_t* __restrict__ Bh_, const uint16_t* __restrict__ Bl_,
                 float* __restrict__ C_, int K, int lda, int ldb, int ldc,
                 long long aO, long long bO, long long cO)
{
    extern __shared__ char sm[];
    const uint32_t sb = smem_u32(sm);
    const int tid = threadIdx.x, lane = tid & 31, wid = tid >> 5;
    const int wm = wid >> 2, wn = wid & 3;
    const int bn0 = blockIdx.x * 128;
    const int bm0 = blockIdx.y * 128;
    const long long z = blockIdx.z;
    const uint16_t* Ah = Ah_ + z * aO + (long long)bm0 * lda;
    const uint16_t* Al = Al_ + z * aO + (long long)bm0 * lda;
    const uint16_t* Bh = Bh_ + z * bO + (long long)bn0 * ldb;
    const uint16_t* Bl = Bl_ + z * bO + (long long)bn0 * ldb;
    float* C = C_ + z * cO;

    float acc[4][4][4];
#pragma unroll
    for (int i = 0; i < 4; ++i)
#pragma unroll
        for (int j = 0; j < 4; ++j)
#pragma unroll
            for (int r = 0; r < 4; ++r) acc[i][j][r] = 0.f;

    const int c8 = tid & 7;
    const int r0 = tid >> 3;
    const int nch = K >> 6;

    uint4 pre[4][4];
#pragma unroll
    for (int i = 0; i < 4; ++i) {
        const int r = r0 + i * 32;
        pre[0][i] = *(const uint4*)&Ah[(long long)r * lda + c8 * 8];
        pre[1][i] = *(const uint4*)&Al[(long long)r * lda + c8 * 8];
        pre[2][i] = *(const uint4*)&Bh[(long long)r * ldb + c8 * 8];
        pre[3][i] = *(const uint4*)&Bl[(long long)r * ldb + c8 * 8];
    }
    {
        char* base = sm;
#pragma unroll
        for (int i = 0; i < 4; ++i) {
            const uint32_t off = (uint32_t)((r0 + i * 32) * 144 + c8 * 16);
            *(uint4*)(base + off)           = pre[0][i];
            *(uint4*)(base + PLB + off)     = pre[1][i];
            *(uint4*)(base + 2 * PLB + off) = pre[2][i];
            *(uint4*)(base + 3 * PLB + off) = pre[3][i];
        }
    }
    __syncthreads();

    const int lrow = lane & 15;
    const int lk   = (lane >> 4) << 3;

    for (int c = 0; c < nch; ++c) {
        const bool more = (c + 1) < nch;
        if (more) {
            const int ko = (c + 1) * 64;
#pragma unroll
            for (int i = 0; i < 4; ++i) {
                const int r = r0 + i * 32;
                pre[0][i] = *(const uint4*)&Ah[(long long)r * lda + ko + c8 * 8];
                pre[1][i] = *(const uint4*)&Al[(long long)r * lda + ko + c8 * 8];
                pre[2][i] = *(const uint4*)&Bh[(long long)r * ldb + ko + c8 * 8];
                pre[3][i] = *(const uint4*)&Bl[(long long)r * ldb + ko + c8 * 8];
            }
        }
        const uint32_t bo = (uint32_t)(c & 1) * 4u * PLB;
#pragma unroll
        for (int ks = 0; ks < 4; ++ks) {
            const int k0 = ks * 16;
            uint32_t Af[4][4], Af2[4][4], Bf[2][4], Bf2[2][4];
#pragma unroll
            for (int i = 0; i < 4; ++i) {
                const uint32_t ro = (uint32_t)((wm * 64 + i * 16 + lrow) * KPAD + k0 + lk) * 2;
                ldsm4(sb + bo + ro, Af[i]);
                ldsm4(sb + bo + PLB + ro, Af2[i]);
            }
#pragma unroll
            for (int jj = 0; jj < 2; ++jj) {
                const uint32_t ro = (uint32_t)((wn * 32 + jj * 16 + lrow) * KPAD + k0 + lk) * 2;
                ldsm4(sb + bo + 2 * PLB + ro, Bf[jj]);
                ldsm4(sb + bo + 3 * PLB + ro, Bf2[jj]);
            }
#pragma unroll
            for (int i = 0; i < 4; ++i)
#pragma unroll
                for (int j = 0; j < 4; ++j) {
                    const int jj = j >> 1, ss = j & 1;
                    mma16816(acc[i][j], Af[i],  Bf[jj][ss],  Bf[jj][ss + 2]);
                    mma16816(acc[i][j], Af[i],  Bf2[jj][ss], Bf2[jj][ss + 2]);
                    mma16816(acc[i][j], Af2[i], Bf[jj][ss],  Bf[jj][ss + 2]);
                }
        }
        if (more) {
            char* base = sm + ((c + 1) & 1) * 4 * PLB;
#pragma unroll
            for (int i = 0; i < 4; ++i) {
                const uint32_t off = (uint32_t)((r0 + i * 32) * 144 + c8 * 16);
                *(uint4*)(base + off)           = pre[0][i];
                *(uint4*)(base + PLB + off)     = pre[1][i];
                *(uint4*)(base + 2 * PLB + off) = pre[2][i];
                *(uint4*)(base + 3 * PLB + off) = pre[3][i];
            }
        }
        __syncthreads();
    }

    const int g  = lane >> 2;
    const int tq = lane & 3;
#pragma unroll
    for (int i = 0; i < 4; ++i)
#pragma unroll
        for (int j = 0; j < 4; ++j) {
            const int row = bm0 + wm * 64 + i * 16 + g;
            const int col = bn0 + wn * 32 + j * 8 + tq * 2;
#pragma unroll
            for (int h = 0; h < 2; ++h) {
                const int rr = row + h * 8;
                float* cp = C + (long long)rr * ldc + col;
                cp[0] = acc[i][j][h * 2 + 0];
                cp[1] = acc[i][j][h * 2 + 1];
            }
        }
}

// ======================= values1: out += w @ vT, K-split x2 (R9) =======================
__global__ void __launch_bounds__(256, 1)
values1_kernel(const uint16_t* __restrict__ Ah_, const uint16_t* __restrict__ Al_,
               const uint16_t* __restrict__ Bh_, const uint16_t* __restrict__ Bl_,
               float* __restrict__ out)
{
    extern __shared__ char sm[];
    const uint32_t sb = smem_u32(sm);
    const int tid = threadIdx.x, lane = tid & 31, wid = tid >> 5;
    const int wm = wid >> 2, wn = wid & 3;
    const int bm0 = blockIdx.y * 128;
    const int b  = blockIdx.z >> 1;
    const int kh = blockIdx.z & 1;
    const int lda = Sq, ldb = Bsz * Sq;
    const uint16_t* Ah = Ah_ + (size_t)b * Sq * Sq + (size_t)bm0 * lda + kh * 512;
    const uint16_t* Al = Al_ + (size_t)b * Sq * Sq + (size_t)bm0 * lda + kh * 512;
    const uint16_t* Bh = Bh_ + (size_t)b * Sq + kh * 512;
    const uint16_t* Bl = Bl_ + (size_t)b * Sq + kh * 512;
    float* C = out + (size_t)b * Sq * Dd;

    float acc[4][4][4];
#pragma unroll
    for (int i = 0; i < 4; ++i)
#pragma unroll
        for (int j = 0; j < 4; ++j)
#pragma unroll
            for (int r = 0; r < 4; ++r) acc[i][j][r] = 0.f;

    const int c8 = tid & 7;
    const int r0 = tid >> 3;
    const int nch = 8;

    uint4 pre[4][4];
#pragma unroll
    for (int i = 0; i < 4; ++i) {
        const int r = r0 + i * 32;
        pre[0][i] = *(const uint4*)&Ah[(long long)r * lda + c8 * 8];
        pre[1][i] = *(const uint4*)&Al[(long long)r * lda + c8 * 8];
        pre[2][i] = *(const uint4*)&Bh[(long long)r * ldb + c8 * 8];
        pre[3][i] = *(const uint4*)&Bl[(long long)r * ldb + c8 * 8];
    }
    {
        char* base = sm;
#pragma unroll
        for (int i = 0; i < 4; ++i) {
            const uint32_t off = (uint32_t)((r0 + i * 32) * 144 + c8 * 16);
            *(uint4*)(base + off)           = pre[0][i];
            *(uint4*)(base + PLB + off)     = pre[1][i];
            *(uint4*)(base + 2 * PLB + off) = pre[2][i];
            *(uint4*)(base + 3 * PLB + off) = pre[3][i];
        }
    }
    __syncthreads();

    const int lrow = lane & 15;
    const int lk   = (lane >> 4) << 3;

    for (int c = 0; c < nch; ++c) {
        const bool more = (c + 1) < nch;
        if (more) {
            const int ko = (c + 1) * 64;
#pragma unroll
            for (int i = 0; i < 4; ++i) {
                const int r = r0 + i * 32;
                pre[0][i] = *(const uint4*)&Ah[(long long)r * lda + ko + c8 * 8];
                pre[1][i] = *(const uint4*)&Al[(long long)r * lda + ko + c8 * 8];
                pre[2][i] = *(const uint4*)&Bh[(long long)r * ldb + ko + c8 * 8];
                pre[3][i] = *(const uint4*)&Bl[(long long)r * ldb + ko + c8 * 8];
            }
        }
        const uint32_t bo = (uint32_t)(c & 1) * 4u * PLB;
#pragma unroll
        for (int ks = 0; ks < 4; ++ks) {
            const int k0 = ks * 16;
            uint32_t Af[4][4], Af2[4][4], Bf[2][4], Bf2[2][4];
#pragma unroll
            for (int i = 0; i < 4; ++i) {
                const uint32_t ro = (uint32_t)((wm * 64 + i * 16 + lrow) * KPAD + k0 + lk) * 2;
                ldsm4(sb + bo + ro, Af[i]);
                ldsm4(sb + bo + PLB + ro, Af2[i]);
            }
#pragma unroll
            for (int jj = 0; jj < 2; ++jj) {
                const uint32_t ro = (uint32_t)((wn * 32 + jj * 16 + lrow) * KPAD + k0 + lk) * 2;
                ldsm4(sb + bo + 2 * PLB + ro, Bf[jj]);
                ldsm4(sb + bo + 3 * PLB + ro, Bf2[jj]);
            }
#pragma unroll
            for (int i = 0; i < 4; ++i)
#pragma unroll
                for (int j = 0; j < 4; ++j) {
                    const int jj = j >> 1, ss = j & 1;
                    mma16816(acc[i][j], Af[i],  Bf[jj][ss],  Bf[jj][ss + 2]);
                    mma16816(acc[i][j], Af[i],  Bf2[jj][ss], Bf2[jj][ss + 2]);
                    mma16816(acc[i][j], Af2[i], Bf[jj][ss],  Bf[jj][ss + 2]);
                }
        }
        if (more) {
            char* base = sm + ((c + 1) & 1) * 4 * PLB;
#pragma unroll
            for (int i = 0; i < 4; ++i) {
                const uint32_t off = (uint32_t)((r0 + i * 32) * 144 + c8 * 16);
                *(uint4*)(base + off)           = pre[0][i];
                *(uint4*)(base + PLB + off)     = pre[1][i];
                *(uint4*)(base + 2 * PLB + off) = pre[2][i];
                *(uint4*)(base + 3 * PLB + off) = pre[3][i];
            }
        }
        __syncthreads();
    }

    const int g  = lane >> 2;
    const int tq = lane & 3;
#pragma unroll
    for (int i = 0; i < 4; ++i)
#pragma unroll
        for (int j = 0; j < 4; ++j) {
            const int row = bm0 + wm * 64 + i * 16 + g;
            const int col = wn * 32 + j * 8 + tq * 2;
#pragma unroll
            for (int h = 0; h < 2; ++h) {
                const int rr = row + h * 8;
                float* cp = C + (long long)rr * Dd + col;
                atomicAdd(cp,     acc[i][j][h * 2 + 0]);
                atomicAdd(cp + 1, acc[i][j][h * 2 + 1]);
            }
        }
}

// ======================= mega kernel (R9 + streaming hints) =======================
constexpr int TPAD   = 136;
constexpr int WROW   = 4240;
constexpr int WSF    = 1060;
constexpr int OFF_QH = 67840, OFF_QL = 72192, OFF_KH = 76544, OFF_KL = 111360;
constexpr int SMEM_MEGA = 146176;

__global__ void __launch_bounds__(256, 1)
mega_kernel(const float* __restrict__ kb, const float* __restrict__ vb,
            const int* __restrict__ mask, const float* __restrict__ scores,
            float* __restrict__ out)
{
    extern __shared__ char sm[];
    const uint32_t sb = smem_u32(sm);
    float* w_s = (float*)sm;
    const int s = blockIdx.x, tid = threadIdx.x;
    const int lane = tid & 31, wid = tid >> 5;
    const int lrow = lane & 15, lk = (lane >> 4) << 3;
    const int g = lane >> 2, tq = lane & 3;

#pragma unroll
    for (int i = 0; i < 2; ++i) {
        int f = tid + i * 256, b = f >> 5, d4 = (f & 31) << 2;
        uint2 hv = *(const uint2*)&g_qh[((size_t)b * Sq + s) * Dd + d4];
        uint2 lv = *(const uint2*)&g_ql[((size_t)b * Sq + s) * Dd + d4];
        uint32_t o = (uint32_t)(b * TPAD + d4) * 2;
        *(uint2*)(sm + OFF_QH + o) = hv;
        *(uint2*)(sm + OFF_QL + o) = lv;
    }
    __syncthreads();
    uint32_t Ah[8][4], Al[8][4];
#pragma unroll
    for (int ks = 0; ks < 8; ++ks) {
        uint32_t ro = (uint32_t)(lrow * TPAD + ks * 16 + lk) * 2;
        ldsm4(sb + OFF_QH + ro, Ah[ks]);
        ldsm4(sb + OFF_QL + ro, Al[ks]);
    }

    float4 pf[16];
    const float* kbs = kb + (long long)s * Sq * Dd;
#pragma unroll
    for (int i = 0; i < 16; ++i) {
        int f = tid + i * 256, tt = f >> 5, d4 = (f & 31) << 2;
        pf[i] = ldcs4(&kbs[(long long)tt * Dd + d4]);
    }
    for (int c = 0; c < 8; ++c) {
#pragma unroll
        for (int i = 0; i < 16; ++i) {
            int f = tid + i * 256, tt = f >> 5, d4 = (f & 31) << 2;
            uint32_t h01, h23, l01, l23; bf16x3_split(pf[i], h01, h23, l01, l23);
            uint32_t o = (uint32_t)(tt * TPAD + d4) * 2;
            *(uint2*)(sm + OFF_KH + o) = make_uint2(h01, h23);
            *(uint2*)(sm + OFF_KL + o) = make_uint2(l01, l23);
        }
        __syncthreads();
        if (c < 7) {
            const float* nx = kbs + (long long)(c + 1) * 128 * Dd;
#pragma unroll
            for (int i = 0; i < 16; ++i) {
                int f = tid + i * 256, tt = f >> 5, d4 = (f & 31) << 2;
                pf[i] = ldcs4(&nx[(long long)tt * Dd + d4]);
            }
        }
        float acc2[2][4] = {};
#pragma unroll
        for (int ks = 0; ks < 8; ++ks) {
            uint32_t Bh[4], Bl[4];
            uint32_t ro = (uint32_t)((wid * 16 + lrow) * TPAD + ks * 16 + lk) * 2;
            ldsm4(sb + OFF_KH + ro, Bh); ldsm4(sb + OFF_KL + ro, Bl);
            mma16816(acc2[0], Ah[ks], Bh[0], Bh[2]);
            mma16816(acc2[0], Ah[ks], Bl[0], Bl[2]);
            mma16816(acc2[0], Al[ks], Bh[0], Bh[2]);
            mma16816(acc2[1], Ah[ks], Bh[1], Bh[3]);
            mma16816(acc2[1], Ah[ks], Bl[1], Bl[3]);
            mma16816(acc2[1], Al[ks], Bh[1], Bh[3]);
        }
#pragma unroll
        for (int j = 0; j < 2; ++j) {
            int col = c * 128 + wid * 16 + j * 8 + tq * 2;
            w_s[g * WSF + col]           = acc2[j][0];
            w_s[g * WSF + col + 1]       = acc2[j][1];
            w_s[(g + 8) * WSF + col]     = acc2[j][2];
            w_s[(g + 8) * WSF + col + 1] = acc2[j][3];
        }
        __syncthreads();
    }

    const float* vbs = vb + (long long)s * Sq * Dd;
#pragma unroll
    for (int i = 0; i < 16; ++i) {
        int f = tid + i * 256, tt = f >> 5, d4 = (f & 31) << 2;
        pf[i] = ldcs4(&vbs[(long long)tt * Dd + d4]);
    }

    const float scale = 0.08838834764831845f;
#pragma unroll 1
    for (int r = 0; r < 2; ++r) {
        const int bb = wid * 2 + r;
        const long long gbase = ((long long)bb * Sq + s) * (long long)Sq;
        float4 vals[8]; float mx = -3e38f;
#pragma unroll
        for (int j2 = 0; j2 < 8; ++j2) {
            int t4 = lane + j2 * 32;
            float4 gsc = ldcs4(&scores[gbase + t4 * 4]);
            float4 ww  = *(const float4*)&w_s[bb * WSF + t4 * 4];
            int4   mk  = *(const int4*)&mask[bb * Sq + t4 * 4];
            float4 v;
            v.x = (gsc.x + ww.x) * scale; if (!mk.x) v.x = -1e9f;
            v.y = (gsc.y + ww.y) * scale; if (!mk.y) v.y = -1e9f;
            v.z = (gsc.z + ww.z) * scale; if (!mk.z) v.z = -1e9f;
            v.w = (gsc.w + ww.w) * scale; if (!mk.w) v.w = -1e9f;
            vals[j2] = v;
            mx = fmaxf(mx, fmaxf(fmaxf(v.x, v.y), fmaxf(v.z, v.w)));
        }
#pragma unroll
        for (int o = 16; o > 0; o >>= 1) mx = fmaxf(mx, __shfl_xor_sync(0xffffffffu, mx, o));
        float sum = 0.f;
#pragma unroll
        for (int j2 = 0; j2 < 8; ++j2) {
            float4 v = vals[j2];
            v.x = __expf(v.x - mx); v.y = __expf(v.y - mx);
            v.z = __expf(v.z - mx); v.w = __expf(v.w - mx);
            vals[j2] = v;
            sum += v.x + v.y + v.z + v.w;
        }
#pragma unroll
        for (int o = 16; o > 0; o >>= 1) sum += __shfl_xor_sync(0xffffffffu, sum, o);
        const float inv = 1.0f / sum;
#pragma unroll
        for (int j2 = 0; j2 < 8; ++j2) {
            int t4 = lane + j2 * 32;
            float4 v = vals[j2];
            v.x *= inv; v.y *= inv; v.z *= inv; v.w *= inv;
            uint32_t h0, l0, h1, l1;
            split2(make_float2(v.x, v.y), h0, l0);
            split2(make_float2(v.z, v.w), h1, l1);
            *(uint2*)(sm + bb * WROW + t4 * 8)        = make_uint2(h0, h1);
            *(uint2*)(sm + bb * WROW + 2048 + t4 * 8) = make_uint2(l0, l1);
            size_t we = (size_t)gbase + (size_t)t4 * 4;
            stcs2(&g_wh[we], make_uint2(h0, h1));
            stcs2(&g_wl[we], make_uint2(l0, l1));
        }
    }
    __syncthreads();

    float acc3[2][4] = {};
    for (int c = 0; c < 8; ++c) {
#pragma unroll
        for (int i = 0; i < 16; ++i) {
            int f = tid + i * 256, tt = f >> 5, d4 = (f & 31) << 2;
            uint32_t h01, h23, l01, l23; bf16x3_split(pf[i], h01, h23, l01, l23);
            uint32_t o = (uint32_t)(tt * TPAD + d4) * 2;
            *(uint2*)(sm + OFF_KH + o) = make_uint2(h01, h23);
            *(uint2*)(sm + OFF_KL + o) = make_uint2(l01, l23);
        }
        __syncthreads();
        if (c < 7) {
            const float* nx = vbs + (long long)(c + 1) * 128 * Dd;
#pragma unroll
            for (int i = 0; i < 16; ++i) {
                int f = tid + i * 256, tt = f >> 5, d4 = (f & 31) << 2;
                pf[i] = ldcs4(&nx[(long long)tt * Dd + d4]);
            }
        }
#pragma unroll
        for (int ks = 0; ks < 8; ++ks) {
            uint32_t A2h[4], A2l[4];
            uint32_t ar = (uint32_t)(lrow * WROW + (c * 128 + ks * 16 + lk) * 2);
            ldsm4(sb + ar, A2h);
            ldsm4(sb + ar + 2048, A2l);
            uint32_t Bh[4], Bl[4];
            uint32_t ro = (uint32_t)((ks * 16 + lrow) * TPAD + wid * 16 + lk) * 2;
            ldsm4t(sb + OFF_KH + ro, Bh);
            ldsm4t(sb + OFF_KL + ro, Bl);
            mma16816(acc3[0], A2h, Bh[0], Bh[1]);
            mma16816(acc3[0], A2h, Bl[0], Bl[1]);
            mma16816(acc3[0], A2l, Bh[0], Bh[1]);
            mma16816(acc3[1], A2h, Bh[2], Bh[3]);
            mma16816(acc3[1], A2h, Bl[2], Bl[3]);
            mma16816(acc3[1], A2l, Bh[2], Bh[3]);
        }
        __syncthreads();
    }
#pragma unroll
    for (int j = 0; j < 2; ++j) {
        const int d = wid * 16 + j * 8 + tq * 2;
        out[((long long)g * Sq + s) * Dd + d]           = acc3[j][0];
        out[((long long)g * Sq + s) * Dd + d + 1]       = acc3[j][1];
        out[((long long)(g + 8) * Sq + s) * Dd + d]     = acc3[j][2];
        out[((long long)(g + 8) * Sq + s) * Dd + d + 1] = acc3[j][3];
    }
}

// ======================= launch =======================
extern "C" void kernel_launch(void* const* d_in, const int* in_sizes, int n_in,
                              void* d_out, int out_size)
{
    const float* query  = (const float*)d_in[0];
    const float* key_   = (const float*)d_in[1];
    const float* value  = (const float*)d_in[2];
    const int*   mask   = (const int*)  d_in[3];
    const float* Wq     = (const float*)d_in[4];
    const float* bq     = (const float*)d_in[5];
    const float* Wk     = (const float*)d_in[6];
    const float* bk     = (const float*)d_in[7];
    const float* Wv     = (const float*)d_in[8];
    const float* bv     = (const float*)d_in[9];
    const float* k_bias = (const float*)d_in[10];
    const float* v_bias = (const float*)d_in[11];
    float* out = (float*)d_out;

    void *pqh, *pql, *pkh, *pkl, *pvh, *pvl, *pwh, *pwl, *ps;
    cudaGetSymbolAddress(&pqh, g_qh);  cudaGetSymbolAddress(&pql, g_ql);
    cudaGetSymbolAddress(&pkh, g_kh);  cudaGetSymbolAddress(&pkl, g_kl);
    cudaGetSymbolAddress(&pvh, g_vTh); cudaGetSymbolAddress(&pvl, g_vTl);
    cudaGetSymbolAddress(&pwh, g_wh);  cudaGetSymbolAddress(&pwl, g_wl);
    cudaGetSymbolAddress(&ps,  g_scores);
    float* sc = (float*)ps;

    cudaFuncSetAttribute(proj_kernel,
                         cudaFuncAttributeMaxDynamicSharedMemorySize, SMEM_GEMM);
    cudaFuncSetAttribute(bf16_gemm_kernel,
                         cudaFuncAttributeMaxDynamicSharedMemorySize, SMEM_GEMM);
    cudaFuncSetAttribute(values1_kernel,
                         cudaFuncAttributeMaxDynamicSharedMemorySize, SMEM_GEMM);
    cudaFuncSetAttribute(mega_kernel,
                         cudaFuncAttributeMaxDynamicSharedMemorySize, SMEM_MEGA);

    dim3 blk(256);

    proj_kernel<<<dim3(1, 128, 3), blk, SMEM_GEMM>>>(
        query, key_, value, Wq, bq, Wk, bk, Wv, bv);

    bf16_gemm_kernel<<<dim3(8, 8, 16), blk, SMEM_GEMM>>>(
        (const uint16_t*)pqh, (const uint16_t*)pql,
        (const uint16_t*)pkh, (const uint16_t*)pkl,
        sc, Dd, Dd, Dd, Sq,
        (long long)Sq * Dd, (long long)Sq * Dd, (long long)Sq * Sq);

    mega_kernel<<<Sq, blk, SMEM_MEGA>>>(k_bias, v_bias, mask, sc, out);

    values1_kernel<<<dim3(1, 8, 32), blk, SMEM_GEMM>>>(
        (const uint16_t*)pwh, (const uint16_t*)pwl,
        (const uint16_t*)pvh, (const uint16_t*)pvl, out);
}

// round 16
// speedup vs baseline: 1.0410x; 1.0410x over previous
#include <cuda_runtime.h>
#include <cuda_bf16.h>
#include <cstdint>

constexpr int Bsz = 16;
constexpr int Sq  = 1024;
constexpr int Hd  = 1024;
constexpr int Dd  = 128;

__device__ uint16_t g_qh[Bsz * Sq * Dd], g_ql[Bsz * Sq * Dd];
__device__ uint16_t g_kh[Bsz * Sq * Dd], g_kl[Bsz * Sq * Dd];
__device__ uint16_t g_vTh[Dd * Bsz * Sq], g_vTl[Dd * Bsz * Sq];   // vT[d][b*S+t]
__device__ uint16_t g_wh[(size_t)Bsz * Sq * Sq], g_wl[(size_t)Bsz * Sq * Sq];
__device__ float    g_scores[(size_t)Bsz * Sq * Sq];

// ======================= helpers =======================
__device__ __forceinline__ uint32_t smem_u32(const void* p) {
    uint32_t a;
    asm("{ .reg .u64 t; cvta.to.shared.u64 t, %1; cvt.u32.u64 %0, t; }" : "=r"(a) : "l"(p));
    return a;
}
__device__ __forceinline__ void ldsm4(uint32_t addr, uint32_t* r) {
    asm volatile("ldmatrix.sync.aligned.m8n8.x4.shared.b16 {%0,%1,%2,%3}, [%4];"
                 : "=r"(r[0]), "=r"(r[1]), "=r"(r[2]), "=r"(r[3]) : "r"(addr));
}
__device__ __forceinline__ void ldsm4t(uint32_t addr, uint32_t* r) {
    asm volatile("ldmatrix.sync.aligned.m8n8.x4.trans.shared.b16 {%0,%1,%2,%3}, [%4];"
                 : "=r"(r[0]), "=r"(r[1]), "=r"(r[2]), "=r"(r[3]) : "r"(addr));
}
__device__ __forceinline__ void mma16816(float* c, const uint32_t* a, uint32_t b0, uint32_t b1) {
    asm volatile(
        "mma.sync.aligned.m16n8k16.row.col.f32.bf16.bf16.f32 "
        "{%0,%1,%2,%3}, {%4,%5,%6,%7}, {%8,%9}, {%0,%1,%2,%3};"
        : "+f"(c[0]), "+f"(c[1]), "+f"(c[2]), "+f"(c[3])
        : "r"(a[0]), "r"(a[1]), "r"(a[2]), "r"(a[3]), "r"(b0), "r"(b1));
}
__device__ __forceinline__ void bf16x3_split(float4 v, uint32_t& h01, uint32_t& h23,
                                             uint32_t& l01, uint32_t& l23) {
    asm("cvt.rn.bf16x2.f32 %0, %1, %2;" : "=r"(h01) : "f"(v.y), "f"(v.x));
    asm("cvt.rn.bf16x2.f32 %0, %1, %2;" : "=r"(h23) : "f"(v.w), "f"(v.z));
    float h0 = __uint_as_float(h01 << 16);
    float h1 = __uint_as_float(h01 & 0xffff0000u);
    float h2 = __uint_as_float(h23 << 16);
    float h3 = __uint_as_float(h23 & 0xffff0000u);
    float l0 = v.x - h0, l1 = v.y - h1, l2 = v.z - h2, l3 = v.w - h3;
    asm("cvt.rn.bf16x2.f32 %0, %1, %2;" : "=r"(l01) : "f"(l1), "f"(l0));
    asm("cvt.rn.bf16x2.f32 %0, %1, %2;" : "=r"(l23) : "f"(l3), "f"(l2));
}
__device__ __forceinline__ void split2(float2 v, uint32_t& h, uint32_t& l) {
    asm("cvt.rn.bf16x2.f32 %0, %1, %2;" : "=r"(h) : "f"(v.y), "f"(v.x));
    float h0 = __uint_as_float(h << 16);
    float h1 = __uint_as_float(h & 0xffff0000u);
    float l0 = v.x - h0, l1 = v.y - h1;
    asm("cvt.rn.bf16x2.f32 %0, %1, %2;" : "=r"(l) : "f"(l1), "f"(l0));
}

constexpr int KPAD = 72;
constexpr int PLB  = 128 * KPAD * 2;
constexpr int SMEM_GEMM = 8 * PLB;   // 147456

// ======================= proj body (device inline, R9 math) =======================
__device__ __forceinline__ void proj_tile(const float* A, const float* Bw,
                                          const float* bias, int z, int bm0,
                                          char* sm, uint32_t sb)
{
    const int tid = threadIdx.x, lane = tid & 31, wid = tid >> 5;
    const int wm = wid >> 2, wn = wid & 3;
    const float* Ab = A + (long long)bm0 * Hd;

    float acc[4][4][4];
#pragma unroll
    for (int i = 0; i < 4; ++i)
#pragma unroll
        for (int j = 0; j < 4; ++j)
#pragma unroll
            for (int r = 0; r < 4; ++r) acc[i][j][r] = 0.f;

    const int r0 = tid >> 4;
    const int c4 = tid & 15;
    const int nch = Hd >> 6;

    float4 ra[8], rb[8];
#pragma unroll
    for (int i = 0; i < 8; ++i) {
        const int r = r0 + i * 16;
        ra[i] = *(const float4*)(Ab + (long long)r * Hd + (c4 << 2));
        rb[i] = *(const float4*)(Bw + (long long)r * Hd + (c4 << 2));
    }
    {
        char* base = sm;
#pragma unroll
        for (int i = 0; i < 8; ++i) {
            const int r = r0 + i * 16;
            const uint32_t off = (uint32_t)(r * KPAD + (c4 << 2)) * 2;
            uint32_t h01, h23, l01, l23;
            bf16x3_split(ra[i], h01, h23, l01, l23);
            *(uint2*)(base + off)       = make_uint2(h01, h23);
            *(uint2*)(base + PLB + off) = make_uint2(l01, l23);
            bf16x3_split(rb[i], h01, h23, l01, l23);
            *(uint2*)(base + 2 * PLB + off) = make_uint2(h01, h23);
            *(uint2*)(base + 3 * PLB + off) = make_uint2(l01, l23);
        }
    }
    __syncthreads();

    const int lrow = lane & 15;
    const int lk   = (lane >> 4) << 3;

    for (int c = 0; c < nch; ++c) {
        const bool more = (c + 1) < nch;
        if (more) {
            const float* Ac = Ab + (c + 1) * 64;
            const float* Bc = Bw + (c + 1) * 64;
#pragma unroll
            for (int i = 0; i < 8; ++i) {
                const int r = r0 + i * 16;
                ra[i] = *(const float4*)(Ac + (long long)r * Hd + (c4 << 2));
                rb[i] = *(const float4*)(Bc + (long long)r * Hd + (c4 << 2));
            }
        }
        const uint32_t bo = (uint32_t)(c & 1) * 4u * PLB;
#pragma unroll
        for (int ks = 0; ks < 4; ++ks) {
            const int k0 = ks * 16;
            uint32_t Ah[4][4], Al[4][4], Bh[2][4], Bl[2][4];
#pragma unroll
            for (int i = 0; i < 4; ++i) {
                const uint32_t ro = (uint32_t)((wm * 64 + i * 16 + lrow) * KPAD + k0 + lk) * 2;
                ldsm4(sb + bo + ro, Ah[i]);
                ldsm4(sb + bo + PLB + ro, Al[i]);
            }
#pragma unroll
            for (int jj = 0; jj < 2; ++jj) {
                const uint32_t ro = (uint32_t)((wn * 32 + jj * 16 + lrow) * KPAD + k0 + lk) * 2;
                ldsm4(sb + bo + 2 * PLB + ro, Bh[jj]);
                ldsm4(sb + bo + 3 * PLB + ro, Bl[jj]);
            }
#pragma unroll
            for (int i = 0; i < 4; ++i)
#pragma unroll
                for (int j = 0; j < 4; ++j) {
                    const int jj = j >> 1, ss = j & 1;
                    mma16816(acc[i][j], Ah[i], Bh[jj][ss], Bh[jj][ss + 2]);
                    mma16816(acc[i][j], Ah[i], Bl[jj][ss], Bl[jj][ss + 2]);
                    mma16816(acc[i][j], Al[i], Bh[jj][ss], Bh[jj][ss + 2]);
                }
        }
        if (more) {
            char* base = sm + ((c + 1) & 1) * 4 * PLB;
#pragma unroll
            for (int i = 0; i < 8; ++i) {
                const int r = r0 + i * 16;
                const uint32_t off = (uint32_t)(r * KPAD + (c4 << 2)) * 2;
                uint32_t h01, h23, l01, l23;
                bf16x3_split(ra[i], h01, h23, l01, l23);
                *(uint2*)(base + off)       = make_uint2(h01, h23);
                *(uint2*)(base + PLB + off) = make_uint2(l01, l23);
                bf16x3_split(rb[i], h01, h23, l01, l23);
                *(uint2*)(base + 2 * PLB + off) = make_uint2(h01, h23);
                *(uint2*)(base + 3 * PLB + off) = make_uint2(l01, l23);
            }
        }
        __syncthreads();
    }

    uint16_t *Oh, *Ol;
    if (z == 0)      { Oh = g_qh;  Ol = g_ql; }
    else if (z == 1) { Oh = g_kh;  Ol = g_kl; }
    else             { Oh = g_vTh; Ol = g_vTl; }
    const int g  = lane >> 2;
    const int tq = lane & 3;
#pragma unroll
    for (int i = 0; i < 4; ++i)
#pragma unroll
        for (int j = 0; j < 4; ++j) {
            const int row = bm0 + wm * 64 + i * 16 + g;
            const int col = wn * 32 + j * 8 + tq * 2;
#pragma unroll
            for (int h = 0; h < 2; ++h) {
                const int rr = row + h * 8;
                float v0 = acc[i][j][h * 2 + 0] + bias[col];
                float v1 = acc[i][j][h * 2 + 1] + bias[col + 1];
                uint32_t hh, ll;
                split2(make_float2(v0, v1), hh, ll);
                if (z < 2) {
                    *(uint32_t*)&Oh[(size_t)rr * Dd + col] = hh;
                    *(uint32_t*)&Ol[(size_t)rr * Dd + col] = ll;
                } else {
                    Oh[(size_t)col * (Bsz * Sq) + rr]       = (uint16_t)(hh & 0xffff);
                    Oh[(size_t)(col + 1) * (Bsz * Sq) + rr] = (uint16_t)(hh >> 16);
                    Ol[(size_t)col * (Bsz * Sq) + rr]       = (uint16_t)(ll & 0xffff);
                    Ol[(size_t)(col + 1) * (Bsz * Sq) + rr] = (uint16_t)(ll >> 16);
                }
            }
        }
}

// ======================= proj_qk kernel (z = 0,1) =======================
__global__ void __launch_bounds__(256, 1)
proj_qk_kernel(const float* __restrict__ query, const float* __restrict__ key_,
               const float* __restrict__ Wq, const float* __restrict__ bq,
               const float* __restrict__ Wk, const float* __restrict__ bk)
{
    extern __shared__ char sm[];
    const uint32_t sb = smem_u32(sm);
    const int z = blockIdx.z;
    const int bm0 = blockIdx.y * 128;
    if (z == 0) proj_tile(query, Wq, bq, 0, bm0, sm, sb);
    else        proj_tile(key_,  Wk, bk, 1, bm0, sm, sb);
}

// ======================= attn1 body (device inline, R9 math) =======================
__device__ __forceinline__ void attn1_tile(const uint16_t* Ah, const uint16_t* Al,
                                           const uint16_t* Bh, const uint16_t* Bl,
                                           float* C, int bn0, int bm0,
                                           char* sm, uint32_t sb)
{
    const int tid = threadIdx.x, lane = tid & 31, wid = tid >> 5;
    const int wm = wid >> 2, wn = wid & 3;
    const int lda = Dd, ldb = Dd, ldc = Sq;
    Ah += (long long)bm0 * lda;  Al += (long long)bm0 * lda;
    Bh += (long long)bn0 * ldb;  Bl += (long long)bn0 * ldb;

    float acc[4][4][4];
#pragma unroll
    for (int i = 0; i < 4; ++i)
#pragma unroll
        for (int j = 0; j < 4; ++j)
#pragma unroll
            for (int r = 0; r < 4; ++r) acc[i][j][r] = 0.f;

    const int c8 = tid & 7;
    const int r0 = tid >> 3;
    const int nch = 2;   // K = 128

    uint4 pre[4][4];
#pragma unroll
    for (int i = 0; i < 4; ++i) {
        const int r = r0 + i * 32;
        pre[0][i] = *(const uint4*)&Ah[(long long)r * lda + c8 * 8];
        pre[1][i] = *(const uint4*)&Al[(long long)r * lda + c8 * 8];
        pre[2][i] = *(const uint4*)&Bh[(long long)r * ldb + c8 * 8];
        pre[3][i] = *(const uint4*)&Bl[(long long)r * ldb + c8 * 8];
    }
    {
        char* base = sm;
#pragma unroll
        for (int i = 0; i < 4; ++i) {
            const uint32_t off = (uint32_t)((r0 + i * 32) * 144 + c8 * 16);
            *(uint4*)(base + off)           = pre[0][i];
            *(uint4*)(base + PLB + off)     = pre[1][i];
            *(uint4*)(base + 2 * PLB + off) = pre[2][i];
            *(uint4*)(base + 3 * PLB + off) = pre[3][i];
        }
    }
    __syncthreads();

    const int lrow = lane & 15;
    const int lk   = (lane >> 4) << 3;

    for (int c = 0; c < nch; ++c) {
        const bool more = (c + 1) < nch;
        if (more) {
            const int ko = (c + 1) * 64;
#pragma unroll
            for (int i = 0; i < 4; ++i) {
                const int r = r0 + i * 32;
                pre[0][i] = *(const uint4*)&Ah[(long long)r * lda + ko + c8 * 8];
                pre[1][i] = *(const uint4*)&Al[(long long)r * lda + ko + c8 * 8];
                pre[2][i] = *(const uint4*)&Bh[(long long)r * ldb + ko + c8 * 8];
                pre[3][i] = *(const uint4*)&Bl[(long long)r * ldb + ko + c8 * 8];
            }
        }
        const uint32_t bo = (uint32_t)(c & 1) * 4u * PLB;
#pragma unroll
        for (int ks = 0; ks < 4; ++ks) {
            const int k0 = ks * 16;
            uint32_t Af[4][4], Af2[4][4], Bf[2][4], Bf2[2][4];
#pragma unroll
            for (int i = 0; i < 4; ++i) {
                const uint32_t ro = (uint32_t)((wm * 64 + i * 16 + lrow) * KPAD + k0 + lk) * 2;
                ldsm4(sb + bo + ro, Af[i]);
                ldsm4(sb + bo + PLB + ro, Af2[i]);
            }
#pragma unroll
            for (int jj = 0; jj < 2; ++jj) {
                const uint32_t ro = (uint32_t)((wn * 32 + jj * 16 + lrow) * KPAD + k0 + lk) * 2;
                ldsm4(sb + bo + 2 * PLB + ro, Bf[jj]);
                ldsm4(sb + bo + 3 * PLB + ro, Bf2[jj]);
            }
#pragma unroll
            for (int i = 0; i < 4; ++i)
#pragma unroll
                for (int j = 0; j < 4; ++j) {
                    const int jj = j >> 1, ss = j & 1;
                    mma16816(acc[i][j], Af[i],  Bf[jj][ss],  Bf[jj][ss + 2]);
                    mma16816(acc[i][j], Af[i],  Bf2[jj][ss], Bf2[jj][ss + 2]);
                    mma16816(acc[i][j], Af2[i], Bf[jj][ss],  Bf[jj][ss + 2]);
                }
        }
        if (more) {
            char* base = sm + ((c + 1) & 1) * 4 * PLB;
#pragma unroll
            for (int i = 0; i < 4; ++i) {
                const uint32_t off = (uint32_t)((r0 + i * 32) * 144 + c8 * 16);
                *(uint4*)(base + off)           = pre[0][i];
                *(uint4*)(base + PLB + off)     = pre[1][i];
                *(uint4*)(base + 2 * PLB + off) = pre[2][i];
                *(uint4*)(base + 3 * PLB + off) = pre[3][i];
            }
        }
        __syncthreads();
    }

    const int g  = lane >> 2;
    const int tq = lane & 3;
#pragma unroll
    for (int i = 0; i < 4; ++i)
#pragma unroll
        for (int j = 0; j < 4; ++j) {
            const int row = bm0 + wm * 64 + i * 16 + g;
            const int col = bn0 + wn * 32 + j * 8 + tq * 2;
#pragma unroll
            for (int h = 0; h < 2; ++h) {
                const int rr = row + h * 8;
                float* cp = C + (long long)rr * ldc + col;
                cp[0] = acc[i][j][h * 2 + 0];
                cp[1] = acc[i][j][h * 2 + 1];
            }
        }
}

// ======================= combined attn1 + proj_v launch ====================
// grid (8,8,18): z<2 -> proj_v tile idx = z*64 + by*8 + bx (scheduled first);
//                z>=2 -> attn1 batch zz = z-2.
__global__ void __launch_bounds__(256, 1)
attn1_projv_kernel(const float* __restrict__ value, const float* __restrict__ Wv,
                   const float* __restrict__ bv, float* __restrict__ scores)
{
    extern __shared__ char sm[];
    const uint32_t sb = smem_u32(sm);
    const int z = blockIdx.z;
    if (z < 2) {
        const int idx = z * 64 + blockIdx.y * 8 + blockIdx.x;
        proj_tile(value, Wv, bv, 2, idx * 128, sm, sb);
    } else {
        const int zz = z - 2;
        attn1_tile(g_qh + (size_t)zz * Sq * Dd, g_ql + (size_t)zz * Sq * Dd,
                   g_kh + (size_t)zz * Sq * Dd, g_kl + (size_t)zz * Sq * Dd,
                   scores + (size_t)zz * Sq * Sq,
                   blockIdx.x * 128, blockIdx.y * 128, sm, sb);
    }
}

// ======================= values1: out += w @ vT, K-split x2 (R9) =======================
__global__ void __launch_bounds__(256, 1)
values1_kernel(const uint16_t* __restrict__ Ah_, const uint16_t* __restrict__ Al_,
               const uint16_t* __restrict__ Bh_, const uint16_t* __restrict__ Bl_,
               float* __restrict__ out)
{
    extern __shared__ char sm[];
    const uint32_t sb = smem_u32(sm);
    const int tid = threadIdx.x, lane = tid & 31, wid = tid >> 5;
    const int wm = wid >> 2, wn = wid & 3;
    const int bm0 = blockIdx.y * 128;
    const int b  = blockIdx.z >> 1;
    const int kh = blockIdx.z & 1;
    const int lda = Sq, ldb = Bsz * Sq;
    const uint16_t* Ah = Ah_ + (size_t)b * Sq * Sq + (size_t)bm0 * lda + kh * 512;
    const uint16_t* Al = Al_ + (size_t)b * Sq * Sq + (size_t)bm0 * lda + kh * 512;
    const uint16_t* Bh = Bh_ + (size_t)b * Sq + kh * 512;
    const uint16_t* Bl = Bl_ + (size_t)b * Sq + kh * 512;
    float* C = out + (size_t)b * Sq * Dd;

    float acc[4][4][4];
#pragma unroll
    for (int i = 0; i < 4; ++i)
#pragma unroll
        for (int j = 0; j < 4; ++j)
#pragma unroll
            for (int r = 0; r < 4; ++r) acc[i][j][r] = 0.f;

    const int c8 = tid & 7;
    const int r0 = tid >> 3;
    const int nch = 8;

    uint4 pre[4][4];
#pragma unroll
    for (int i = 0; i < 4; ++i) {
        const int r = r0 + i * 32;
        pre[0][i] = *(const uint4*)&Ah[(long long)r * lda + c8 * 8];
        pre[1][i] = *(const uint4*)&Al[(long long)r * lda + c8 * 8];
        pre[2][i] = *(const uint4*)&Bh[(long long)r * ldb + c8 * 8];
        pre[3][i] = *(const uint4*)&Bl[(long long)r * ldb + c8 * 8];
    }
    {
        char* base = sm;
#pragma unroll
        for (int i = 0; i < 4; ++i) {
            const uint32_t off = (uint32_t)((r0 + i * 32) * 144 + c8 * 16);
            *(uint4*)(base + off)           = pre[0][i];
            *(uint4*)(base + PLB + off)     = pre[1][i];
            *(uint4*)(base + 2 * PLB + off) = pre[2][i];
            *(uint4*)(base + 3 * PLB + off) = pre[3][i];
        }
    }
    __syncthreads();

    const int lrow = lane & 15;
    const int lk   = (lane >> 4) << 3;

    for (int c = 0; c < nch; ++c) {
        const bool more = (c + 1) < nch;
        if (more) {
            const int ko = (c + 1) * 64;
#pragma unroll
            for (int i = 0; i < 4; ++i) {
                const int r = r0 + i * 32;
                pre[0][i] = *(const uint4*)&Ah[(long long)r * lda + ko + c8 * 8];
                pre[1][i] = *(const uint4*)&Al[(long long)r * lda + ko + c8 * 8];
                pre[2][i] = *(const uint4*)&Bh[(long long)r * ldb + ko + c8 * 8];
                pre[3][i] = *(const uint4*)&Bl[(long long)r * ldb + ko + c8 * 8];
            }
        }
        const uint32_t bo = (uint32_t)(c & 1) * 4u * PLB;
#pragma unroll
        for (int ks = 0; ks < 4; ++ks) {
            const int k0 = ks * 16;
            uint32_t Af[4][4], Af2[4][4], Bf[2][4], Bf2[2][4];
#pragma unroll
            for (int i = 0; i < 4; ++i) {
                const uint32_t ro = (uint32_t)((wm * 64 + i * 16 + lrow) * KPAD + k0 + lk) * 2;
                ldsm4(sb + bo + ro, Af[i]);
                ldsm4(sb + bo + PLB + ro, Af2[i]);
            }
#pragma unroll
            for (int jj = 0; jj < 2; ++jj) {
                const uint32_t ro = (uint32_t)((wn * 32 + jj * 16 + lrow) * KPAD + k0 + lk) * 2;
                ldsm4(sb + bo + 2 * PLB + ro, Bf[jj]);
                ldsm4(sb + bo + 3 * PLB + ro, Bf2[jj]);
            }
#pragma unroll
            for (int i = 0; i < 4; ++i)
#pragma unroll
                for (int j = 0; j < 4; ++j) {
                    const int jj = j >> 1, ss = j & 1;
                    mma16816(acc[i][j], Af[i],  Bf[jj][ss],  Bf[jj][ss + 2]);
                    mma16816(acc[i][j], Af[i],  Bf2[jj][ss], Bf2[jj][ss + 2]);
                    mma16816(acc[i][j], Af2[i], Bf[jj][ss],  Bf[jj][ss + 2]);
                }
        }
        if (more) {
            char* base = sm + ((c + 1) & 1) * 4 * PLB;
#pragma unroll
            for (int i = 0; i < 4; ++i) {
                const uint32_t off = (uint32_t)((r0 + i * 32) * 144 + c8 * 16);
                *(uint4*)(base + off)           = pre[0][i];
                *(uint4*)(base + PLB + off)     = pre[1][i];
                *(uint4*)(base + 2 * PLB + off) = pre[2][i];
                *(uint4*)(base + 3 * PLB + off) = pre[3][i];
            }
        }
        __syncthreads();
    }

    const int g  = lane >> 2;
    const int tq = lane & 3;
#pragma unroll
    for (int i = 0; i < 4; ++i)
#pragma unroll
        for (int j = 0; j < 4; ++j) {
            const int row = bm0 + wm * 64 + i * 16 + g;
            const int col = wn * 32 + j * 8 + tq * 2;
#pragma unroll
            for (int h = 0; h < 2; ++h) {
                const int rr = row + h * 8;
                float* cp = C + (long long)rr * Dd + col;
                atomicAdd(cp,     acc[i][j][h * 2 + 0]);
                atomicAdd(cp + 1, acc[i][j][h * 2 + 1]);
            }
        }
}

// ======================= mega kernel (R9, unchanged) =======================
constexpr int TPAD   = 136;
constexpr int WROW   = 4240;
constexpr int WSF    = 1060;
constexpr int OFF_QH = 67840, OFF_QL = 72192, OFF_KH = 76544, OFF_KL = 111360;
constexpr int SMEM_MEGA = 146176;

__global__ void __launch_bounds__(256, 1)
mega_kernel(const float* __restrict__ kb, const float* __restrict__ vb,
            const int* __restrict__ mask, const float* __restrict__ scores,
            float* __restrict__ out)
{
    extern __shared__ char sm[];
    const uint32_t sb = smem_u32(sm);
    float* w_s = (float*)sm;
    const int s = blockIdx.x, tid = threadIdx.x;
    const int lane = tid & 31, wid = tid >> 5;
    const int lrow = lane & 15, lk = (lane >> 4) << 3;
    const int g = lane >> 2, tq = lane & 3;

#pragma unroll
    for (int i = 0; i < 2; ++i) {
        int f = tid + i * 256, b = f >> 5, d4 = (f & 31) << 2;
        uint2 hv = *(const uint2*)&g_qh[((size_t)b * Sq + s) * Dd + d4];
        uint2 lv = *(const uint2*)&g_ql[((size_t)b * Sq + s) * Dd + d4];
        uint32_t o = (uint32_t)(b * TPAD + d4) * 2;
        *(uint2*)(sm + OFF_QH + o) = hv;
        *(uint2*)(sm + OFF_QL + o) = lv;
    }
    __syncthreads();
    uint32_t Ah[8][4], Al[8][4];
#pragma unroll
    for (int ks = 0; ks < 8; ++ks) {
        uint32_t ro = (uint32_t)(lrow * TPAD + ks * 16 + lk) * 2;
        ldsm4(sb + OFF_QH + ro, Ah[ks]);
        ldsm4(sb + OFF_QL + ro, Al[ks]);
    }

    float4 pf[16];
    const float* kbs = kb + (long long)s * Sq * Dd;
#pragma unroll
    for (int i = 0; i < 16; ++i) {
        int f = tid + i * 256, tt = f >> 5, d4 = (f & 31) << 2;
        pf[i] = *(const float4*)&kbs[(long long)tt * Dd + d4];
    }
    for (int c = 0; c < 8; ++c) {
#pragma unroll
        for (int i = 0; i < 16; ++i) {
            int f = tid + i * 256, tt = f >> 5, d4 = (f & 31) << 2;
            uint32_t h01, h23, l01, l23; bf16x3_split(pf[i], h01, h23, l01, l23);
            uint32_t o = (uint32_t)(tt * TPAD + d4) * 2;
            *(uint2*)(sm + OFF_KH + o) = make_uint2(h01, h23);
            *(uint2*)(sm + OFF_KL + o) = make_uint2(l01, l23);
        }
        __syncthreads();
        if (c < 7) {
            const float* nx = kbs + (long long)(c + 1) * 128 * Dd;
#pragma unroll
            for (int i = 0; i < 16; ++i) {
                int f = tid + i * 256, tt = f >> 5, d4 = (f & 31) << 2;
                pf[i] = *(const float4*)&nx[(long long)tt * Dd + d4];
            }
        }
        float acc2[2][4] = {};
#pragma unroll
        for (int ks = 0; ks < 8; ++ks) {
            uint32_t Bh[4], Bl[4];
            uint32_t ro = (uint32_t)((wid * 16 + lrow) * TPAD + ks * 16 + lk) * 2;
            ldsm4(sb + OFF_KH + ro, Bh); ldsm4(sb + OFF_KL + ro, Bl);
            mma16816(acc2[0], Ah[ks], Bh[0], Bh[2]);
            mma16816(acc2[0], Ah[ks], Bl[0], Bl[2]);
            mma16816(acc2[0], Al[ks], Bh[0], Bh[2]);
            mma16816(acc2[1], Ah[ks], Bh[1], Bh[3]);
            mma16816(acc2[1], Ah[ks], Bl[1], Bl[3]);
            mma16816(acc2[1], Al[ks], Bh[1], Bh[3]);
        }
#pragma unroll
        for (int j = 0; j < 2; ++j) {
            int col = c * 128 + wid * 16 + j * 8 + tq * 2;
            w_s[g * WSF + col]           = acc2[j][0];
            w_s[g * WSF + col + 1]       = acc2[j][1];
            w_s[(g + 8) * WSF + col]     = acc2[j][2];
            w_s[(g + 8) * WSF + col + 1] = acc2[j][3];
        }
        __syncthreads();
    }

    const float* vbs = vb + (long long)s * Sq * Dd;
#pragma unroll
    for (int i = 0; i < 16; ++i) {
        int f = tid + i * 256, tt = f >> 5, d4 = (f & 31) << 2;
        pf[i] = *(const float4*)&vbs[(long long)tt * Dd + d4];
    }

    const float scale = 0.08838834764831845f;
#pragma unroll 1
    for (int r = 0; r < 2; ++r) {
        const int bb = wid * 2 + r;
        const long long gbase = ((long long)bb * Sq + s) * (long long)Sq;
        float4 vals[8]; float mx = -3e38f;
#pragma unroll
        for (int j2 = 0; j2 < 8; ++j2) {
            int t4 = lane + j2 * 32;
            float4 gsc = *(const float4*)&scores[gbase + t4 * 4];
            float4 ww  = *(const float4*)&w_s[bb * WSF + t4 * 4];
            int4   mk  = *(const int4*)&mask[bb * Sq + t4 * 4];
            float4 v;
            v.x = (gsc.x + ww.x) * scale; if (!mk.x) v.x = -1e9f;
            v.y = (gsc.y + ww.y) * scale; if (!mk.y) v.y = -1e9f;
            v.z = (gsc.z + ww.z) * scale; if (!mk.z) v.z = -1e9f;
            v.w = (gsc.w + ww.w) * scale; if (!mk.w) v.w = -1e9f;
            vals[j2] = v;
            mx = fmaxf(mx, fmaxf(fmaxf(v.x, v.y), fmaxf(v.z, v.w)));
        }
#pragma unroll
        for (int o = 16; o > 0; o >>= 1) mx = fmaxf(mx, __shfl_xor_sync(0xffffffffu, mx, o));
        float sum = 0.f;
#pragma unroll
        for (int j2 = 0; j2 < 8; ++j2) {
            float4 v = vals[j2];
            v.x = __expf(v.x - mx); v.y = __expf(v.y - mx);
            v.z = __expf(v.z - mx); v.w = __expf(v.w - mx);
            vals[j2] = v;
            sum += v.x + v.y + v.z + v.w;
        }
#pragma unroll
        for (int o = 16; o > 0; o >>= 1) sum += __shfl_xor_sync(0xffffffffu, sum, o);
        const float inv = 1.0f / sum;
#pragma unroll
        for (int j2 = 0; j2 < 8; ++j2) {
            int t4 = lane + j2 * 32;
            float4 v = vals[j2];
            v.x *= inv; v.y *= inv; v.z *= inv; v.w *= inv;
            uint32_t h0, l0, h1, l1;
            split2(make_float2(v.x, v.y), h0, l0);
            split2(make_float2(v.z, v.w), h1, l1);
            *(uint2*)(sm + bb * WROW + t4 * 8)        = make_uint2(h0, h1);
            *(uint2*)(sm + bb * WROW + 2048 + t4 * 8) = make_uint2(l0, l1);
            size_t we = (size_t)gbase + (size_t)t4 * 4;
            *(uint2*)&g_wh[we] = make_uint2(h0, h1);
            *(uint2*)&g_wl[we] = make_uint2(l0, l1);
        }
    }
    __syncthreads();

    float acc3[2][4] = {};
    for (int c = 0; c < 8; ++c) {
#pragma unroll
        for (int i = 0; i < 16; ++i) {
            int f = tid + i * 256, tt = f >> 5, d4 = (f & 31) << 2;
            uint32_t h01, h23, l01, l23; bf16x3_split(pf[i], h01, h23, l01, l23);
            uint32_t o = (uint32_t)(tt * TPAD + d4) * 2;
            *(uint2*)(sm + OFF_KH + o) = make_uint2(h01, h23);
            *(uint2*)(sm + OFF_KL + o) = make_uint2(l01, l23);
        }
        __syncthreads();
        if (c < 7) {
            const float* nx = vbs + (long long)(c + 1) * 128 * Dd;
#pragma unroll
            for (int i = 0; i < 16; ++i) {
                int f = tid + i * 256, tt = f >> 5, d4 = (f & 31) << 2;
                pf[i] = *(const float4*)&nx[(long long)tt * Dd + d4];
            }
        }
#pragma unroll
        for (int ks = 0; ks < 8; ++ks) {
            uint32_t A2h[4], A2l[4];
            uint32_t ar = (uint32_t)(lrow * WROW + (c * 128 + ks * 16 + lk) * 2);
            ldsm4(sb + ar, A2h);
            ldsm4(sb + ar + 2048, A2l);
            uint32_t Bh[4], Bl[4];
            uint32_t ro = (uint32_t)((ks * 16 + lrow) * TPAD + wid * 16 + lk) * 2;
            ldsm4t(sb + OFF_KH + ro, Bh);
            ldsm4t(sb + OFF_KL + ro, Bl);
            mma16816(acc3[0], A2h, Bh[0], Bh[1]);
            mma16816(acc3[0], A2h, Bl[0], Bl[1]);
            mma16816(acc3[0], A2l, Bh[0], Bh[1]);
            mma16816(acc3[1], A2h, Bh[2], Bh[3]);
            mma16816(acc3[1], A2h, Bl[2], Bl[3]);
            mma16816(acc3[1], A2l, Bh[2], Bh[3]);
        }
        __syncthreads();
    }
#pragma unroll
    for (int j = 0; j < 2; ++j) {
        const int d = wid * 16 + j * 8 + tq * 2;
        out[((long long)g * Sq + s) * Dd + d]           = acc3[j][0];
        out[((long long)g * Sq + s) * Dd + d + 1]       = acc3[j][1];
        out[((long long)(g + 8) * Sq + s) * Dd + d]     = acc3[j][2];
        out[((long long)(g + 8) * Sq + s) * Dd + d + 1] = acc3[j][3];
    }
}

// ======================= launch =======================
extern "C" void kernel_launch(void* const* d_in, const int* in_sizes, int n_in,
                              void* d_out, int out_size)
{
    const float* query  = (const float*)d_in[0];
    const float* key_   = (const float*)d_in[1];
    const float* value  = (const float*)d_in[2];
    const int*   mask   = (const int*)  d_in[3];
    const float* Wq     = (const float*)d_in[4];
    const float* bq     = (const float*)d_in[5];
    const float* Wk     = (const float*)d_in[6];
    const float* bk     = (const float*)d_in[7];
    const float* Wv     = (const float*)d_in[8];
    const float* bv     = (const float*)d_in[9];
    const float* k_bias = (const float*)d_in[10];
    const float* v_bias = (const float*)d_in[11];
    float* out = (float*)d_out;

    void *pvh, *pvl, *pwh, *pwl, *ps;
    cudaGetSymbolAddress(&pvh, g_vTh); cudaGetSymbolAddress(&pvl, g_vTl);
    cudaGetSymbolAddress(&pwh, g_wh);  cudaGetSymbolAddress(&pwl, g_wl);
    cudaGetSymbolAddress(&ps,  g_scores);
    float* sc = (float*)ps;

    cudaFuncSetAttribute(proj_qk_kernel,
                         cudaFuncAttributeMaxDynamicSharedMemorySize, SMEM_GEMM);
    cudaFuncSetAttribute(attn1_projv_kernel,
                         cudaFuncAttributeMaxDynamicSharedMemorySize, SMEM_GEMM);
    cudaFuncSetAttribute(values1_kernel,
                         cudaFuncAttributeMaxDynamicSharedMemorySize, SMEM_GEMM);
    cudaFuncSetAttribute(mega_kernel,
                         cudaFuncAttributeMaxDynamicSharedMemorySize, SMEM_MEGA);

    dim3 blk(256);

    // q,k projections
    proj_qk_kernel<<<dim3(1, 128, 2), blk, SMEM_GEMM>>>(
        query, key_, Wq, bq, Wk, bk);

    // combined: v projection (z=0,1; scheduled first) + attn1 (z=2..17)
    attn1_projv_kernel<<<dim3(8, 8, 18), blk, SMEM_GEMM>>>(
        value, Wv, bv, sc);

    // mega: attn2 + softmax (writes w planes) + values2
    mega_kernel<<<Sq, blk, SMEM_MEGA>>>(k_bias, v_bias, mask, sc, out);

    // values1: out += w @ vT
    values1_kernel<<<dim3(1, 8, 32), blk, SMEM_GEMM>>>(
        (const uint16_t*)pwh, (const uint16_t*)pwl,
        (const uint16_t*)pvh, (const uint16_t*)pvl, out);
}